// round 1
// baseline (speedup 1.0000x reference)
#include <cuda_runtime.h>

// Problem constants
#define S_LEN 1024
#define BATCH 2
#define DM    768
#define NH    12
#define HD    64
#define NTILE 16          // S_LEN / 64 query tiles

// Scratch (device globals — no allocation allowed)
__device__ float g_q[BATCH * S_LEN * DM];
__device__ float g_k[BATCH * S_LEN * DM];
__device__ float g_v[BATCH * S_LEN * DM];
__device__ float g_part[BATCH * NTILE * DM];   // per-tile pooled partial sums

// ---------------------------------------------------------------------------
// QKV GEMM: C = A(2048x768) @ W(768x768) + bias, blockIdx.z selects Q/K/V.
// 64x64 tile, BK=16, 256 threads, 4x4 per thread.
// ---------------------------------------------------------------------------
__global__ __launch_bounds__(256) void qkv_gemm(
    const float* __restrict__ A,
    const float* __restrict__ Wq, const float* __restrict__ bq,
    const float* __restrict__ Wk, const float* __restrict__ bk,
    const float* __restrict__ Wv, const float* __restrict__ bv)
{
    const float* W; const float* bias; float* C;
    if (blockIdx.z == 0)      { W = Wq; bias = bq; C = g_q; }
    else if (blockIdx.z == 1) { W = Wk; bias = bk; C = g_k; }
    else                      { W = Wv; bias = bv; C = g_v; }

    __shared__ float As[16 * 68];   // [k][m], padded stride 68 (16B-aligned, conflict-free)
    __shared__ float Bs[16 * 64];   // [k][n]

    const int tid = threadIdx.x;
    const int tx  = tid & 15;       // n-group
    const int ty  = tid >> 4;       // m-group
    const int m0  = blockIdx.y * 64;
    const int n0  = blockIdx.x * 64;

    const int aRow = tid >> 2;            // 0..63
    const int aK4  = (tid & 3) << 2;      // 0,4,8,12
    const int bRow = tid >> 4;            // 0..15
    const int bN4  = (tid & 15) << 2;     // 0..60

    float acc[4][4];
    #pragma unroll
    for (int i = 0; i < 4; i++)
        #pragma unroll
        for (int j = 0; j < 4; j++) acc[i][j] = 0.0f;

    for (int k0 = 0; k0 < DM; k0 += 16) {
        float4 av = *(const float4*)&A[(m0 + aRow) * DM + k0 + aK4];
        float4 bv = *(const float4*)&W[(k0 + bRow) * DM + n0 + bN4];
        __syncthreads();
        As[(aK4 + 0) * 68 + aRow] = av.x;
        As[(aK4 + 1) * 68 + aRow] = av.y;
        As[(aK4 + 2) * 68 + aRow] = av.z;
        As[(aK4 + 3) * 68 + aRow] = av.w;
        *(float4*)&Bs[bRow * 64 + bN4] = bv;
        __syncthreads();

        #pragma unroll
        for (int kk = 0; kk < 16; kk++) {
            float4 a4 = *(const float4*)&As[kk * 68 + ty * 4];
            float4 b4 = *(const float4*)&Bs[kk * 64 + tx * 4];
            float ar[4] = {a4.x, a4.y, a4.z, a4.w};
            float br[4] = {b4.x, b4.y, b4.z, b4.w};
            #pragma unroll
            for (int i = 0; i < 4; i++)
                #pragma unroll
                for (int j = 0; j < 4; j++)
                    acc[i][j] = fmaf(ar[i], br[j], acc[i][j]);
        }
    }

    float4 bias4 = *(const float4*)&bias[n0 + tx * 4];
    #pragma unroll
    for (int i = 0; i < 4; i++) {
        int m = m0 + ty * 4 + i;
        float4 r;
        r.x = acc[i][0] + bias4.x;
        r.y = acc[i][1] + bias4.y;
        r.z = acc[i][2] + bias4.z;
        r.w = acc[i][3] + bias4.w;
        *(float4*)&C[m * DM + n0 + tx * 4] = r;
    }
}

// ---------------------------------------------------------------------------
// Windowed attention per (tile of 64 queries, head, batch) + per-tile pooling.
// smem: q(64x68) | k(128x68) | v(128x68) | attn(64x68)  = 104448 B dynamic
// 256 threads: 4 threads per query (sub = lane%4 handles every-4th window pos,
// and 16 of 64 output dims).
// ---------------------------------------------------------------------------
__global__ __launch_bounds__(256) void attn_kernel()
{
    const int tile = blockIdx.x;   // 0..15
    const int h    = blockIdx.y;   // 0..11
    const int b    = blockIdx.z;   // 0..1
    const int s0   = tile * 64;
    const int colbase = h * HD;

    extern __shared__ float sm[];
    float* q_sm = sm;                    // 64*68
    float* k_sm = q_sm + 64 * 68;        // 128*68
    float* v_sm = k_sm + 128 * 68;       // 128*68
    float* a_sm = v_sm + 128 * 68;       // 64*68 (scores/attn, then reduce buf)

    const int tid = threadIdx.x;

    // Load Q tile (64 rows x 64 dims)
    for (int i = tid; i < 64 * 16; i += 256) {
        int row = i >> 4;
        int c4  = (i & 15) << 2;
        float4 v = *(const float4*)&g_q[((b * S_LEN) + s0 + row) * DM + colbase + c4];
        *(float4*)&q_sm[row * 68 + c4] = v;
    }
    // Load K/V window (rows s0-32 .. s0+95), zero-fill out of range
    for (int i = tid; i < 128 * 16; i += 256) {
        int row  = i >> 4;
        int c4   = (i & 15) << 2;
        int srow = s0 - 32 + row;
        float4 kv = make_float4(0.f, 0.f, 0.f, 0.f);
        float4 vv = make_float4(0.f, 0.f, 0.f, 0.f);
        if (srow >= 0 && srow < S_LEN) {
            kv = *(const float4*)&g_k[((b * S_LEN) + srow) * DM + colbase + c4];
            vv = *(const float4*)&g_v[((b * S_LEN) + srow) * DM + colbase + c4];
        }
        *(float4*)&k_sm[row * 68 + c4] = kv;
        *(float4*)&v_sm[row * 68 + c4] = vv;
    }
    __syncthreads();

    const int qi  = tid >> 2;       // query within tile
    const int sub = tid & 3;        // sub-lane within query group
    const int sglob = s0 + qi;

    // ---- scores for window positions w = sub, sub+4, ... (<=64) ----
    float sc[17];
    const int nw = (sub == 0) ? 17 : 16;
    const float* qr = &q_sm[qi * 68];
    for (int j = 0; j < nw; j++) {
        int w = sub + 4 * j;
        const float* kr = &k_sm[(qi + w) * 68];
        float s = 0.f;
        #pragma unroll
        for (int dc = 0; dc < 16; dc++) {
            float4 qv = *(const float4*)&qr[dc * 4];
            float4 kv = *(const float4*)&kr[dc * 4];
            s = fmaf(qv.x, kv.x, s);
            s = fmaf(qv.y, kv.y, s);
            s = fmaf(qv.z, kv.z, s);
            s = fmaf(qv.w, kv.w, s);
        }
        int ks = sglob - 32 + w;
        sc[j] = (ks >= 0 && ks < S_LEN) ? s * 0.125f : -1e9f;
    }

    // ---- softmax across the 4-lane group ----
    float m = -1e30f;
    for (int j = 0; j < nw; j++) m = fmaxf(m, sc[j]);
    m = fmaxf(m, __shfl_xor_sync(0xffffffffu, m, 1));
    m = fmaxf(m, __shfl_xor_sync(0xffffffffu, m, 2));
    float lsum = 0.f;
    for (int j = 0; j < nw; j++) { sc[j] = __expf(sc[j] - m); lsum += sc[j]; }
    lsum += __shfl_xor_sync(0xffffffffu, lsum, 1);
    lsum += __shfl_xor_sync(0xffffffffu, lsum, 2);
    float rinv = 1.0f / lsum;
    for (int j = 0; j < nw; j++)
        a_sm[qi * 68 + sub + 4 * j] = sc[j] * rinv;
    __syncthreads();

    // ---- out[qi][d0..d0+15] = sum_w attn * v ----
    const int d0 = sub * 16;
    float4 acc0 = make_float4(0.f, 0.f, 0.f, 0.f);
    float4 acc1 = acc0, acc2 = acc0, acc3 = acc0;
    const float* ar = &a_sm[qi * 68];
    for (int w = 0; w < 65; w++) {
        float p = ar[w];
        const float* vr = &v_sm[(qi + w) * 68 + d0];
        float4 v0 = *(const float4*)&vr[0];
        float4 v1 = *(const float4*)&vr[4];
        float4 v2 = *(const float4*)&vr[8];
        float4 v3 = *(const float4*)&vr[12];
        acc0.x = fmaf(p, v0.x, acc0.x); acc0.y = fmaf(p, v0.y, acc0.y);
        acc0.z = fmaf(p, v0.z, acc0.z); acc0.w = fmaf(p, v0.w, acc0.w);
        acc1.x = fmaf(p, v1.x, acc1.x); acc1.y = fmaf(p, v1.y, acc1.y);
        acc1.z = fmaf(p, v1.z, acc1.z); acc1.w = fmaf(p, v1.w, acc1.w);
        acc2.x = fmaf(p, v2.x, acc2.x); acc2.y = fmaf(p, v2.y, acc2.y);
        acc2.z = fmaf(p, v2.z, acc2.z); acc2.w = fmaf(p, v2.w, acc2.w);
        acc3.x = fmaf(p, v3.x, acc3.x); acc3.y = fmaf(p, v3.y, acc3.y);
        acc3.z = fmaf(p, v3.z, acc3.z); acc3.w = fmaf(p, v3.w, acc3.w);
    }

    // Store per-query outputs into q_sm (safe: q_sm reads ended before prior barrier)
    *(float4*)&q_sm[qi * 68 + d0 + 0]  = acc0;
    *(float4*)&q_sm[qi * 68 + d0 + 4]  = acc1;
    *(float4*)&q_sm[qi * 68 + d0 + 8]  = acc2;
    *(float4*)&q_sm[qi * 68 + d0 + 12] = acc3;
    __syncthreads();

    // ---- pooled partial: sum over the 64 queries in this tile ----
    const int d    = tid & 63;
    const int part = tid >> 6;
    float s = 0.f;
    #pragma unroll
    for (int r = part * 16; r < part * 16 + 16; r++)
        s += q_sm[r * 68 + d];
    a_sm[part * 64 + d] = s;
    __syncthreads();
    if (tid < 64) {
        float tot = a_sm[tid] + a_sm[64 + tid] + a_sm[128 + tid] + a_sm[192 + tid];
        g_part[((b * NTILE) + tile) * DM + h * HD + tid] = tot;
    }
}

// ---------------------------------------------------------------------------
// Final FC: out[b][o] = relu( (mean_s out_attn)[b] @ Wfc + bfc )
// grid (3, 2), 256 threads; each block recomputes pooled (cheap) into smem.
// ---------------------------------------------------------------------------
__global__ __launch_bounds__(256) void fc_kernel(
    const float* __restrict__ Wfc, const float* __restrict__ bfc,
    float* __restrict__ out)
{
    __shared__ float pooled[DM];
    const int b   = blockIdx.y;
    const int tid = threadIdx.x;

    for (int i = tid; i < DM; i += 256) {
        float s = 0.f;
        #pragma unroll
        for (int t = 0; t < NTILE; t++)
            s += g_part[(b * NTILE + t) * DM + i];
        pooled[i] = s * (1.0f / (float)S_LEN);
    }
    __syncthreads();

    const int o = blockIdx.x * 256 + tid;
    float acc = bfc[o];
    for (int i = 0; i < DM; i++)
        acc = fmaf(pooled[i], Wfc[i * DM + o], acc);
    out[b * DM + o] = fmaxf(acc, 0.f);
}

// ---------------------------------------------------------------------------
extern "C" void kernel_launch(void* const* d_in, const int* in_sizes, int n_in,
                              void* d_out, int out_size)
{
    const float* x   = (const float*)d_in[0];
    const float* Wq  = (const float*)d_in[1];
    const float* bq  = (const float*)d_in[2];
    const float* Wk  = (const float*)d_in[3];
    const float* bk  = (const float*)d_in[4];
    const float* Wv  = (const float*)d_in[5];
    const float* bv  = (const float*)d_in[6];
    const float* Wfc = (const float*)d_in[7];
    const float* bfc = (const float*)d_in[8];
    float* out = (float*)d_out;

    // QKV projections
    dim3 gg(DM / 64, (BATCH * S_LEN) / 64, 3);
    qkv_gemm<<<gg, 256>>>(x, Wq, bq, Wk, bk, Wv, bv);

    // Windowed attention + per-tile pooling (104448 B dynamic smem)
    const int attn_smem = (64 + 128 + 128 + 64) * 68 * (int)sizeof(float);
    cudaFuncSetAttribute(attn_kernel,
                         cudaFuncAttributeMaxDynamicSharedMemorySize, attn_smem);
    attn_kernel<<<dim3(NTILE, NH, BATCH), 256, attn_smem>>>();

    // Pool + FC + relu
    fc_kernel<<<dim3(3, BATCH), 256>>>(Wfc, bfc, out);
}

// round 2
// speedup vs baseline: 1.1209x; 1.1209x over previous
#include <cuda_runtime.h>

// Problem constants
#define S_LEN 1024
#define BATCH 2
#define DM    768
#define NH    12
#define HD    64
#define NTILE 16          // S_LEN / 64 query tiles

// Scratch (device globals — no allocation allowed)
__device__ float g_q[BATCH * S_LEN * DM];
__device__ float g_k[BATCH * S_LEN * DM];
__device__ float g_v[BATCH * S_LEN * DM];
__device__ float g_part[BATCH * NTILE * DM];   // per-tile pooled partial sums

// ---------------------------------------------------------------------------
// QKV GEMM: C = A(2048x768) @ W(768x768) + bias, blockIdx.z selects Q/K/V.
// 128x128 tile, BK=16, 256 threads, 8x8 per thread, register prefetch.
// ---------------------------------------------------------------------------
__global__ __launch_bounds__(256, 2) void qkv_gemm(
    const float* __restrict__ A,
    const float* __restrict__ Wq, const float* __restrict__ bq,
    const float* __restrict__ Wk, const float* __restrict__ bk,
    const float* __restrict__ Wv, const float* __restrict__ bv)
{
    const float* W; const float* bias; float* C;
    if (blockIdx.z == 0)      { W = Wq; bias = bq; C = g_q; }
    else if (blockIdx.z == 1) { W = Wk; bias = bk; C = g_k; }
    else                      { W = Wv; bias = bv; C = g_v; }

    __shared__ float As[16 * 132];   // [k][m], padded stride 132
    __shared__ float Bs[16 * 128];   // [k][n]

    const int tid = threadIdx.x;
    const int tx  = tid & 15;        // n-group (8 cols each)
    const int ty  = tid >> 4;        // m-group (8 rows each)
    const int m0  = blockIdx.y * 128;
    const int n0  = blockIdx.x * 128;

    // A loader: row = tid>>1 (0..127), cols aC..aC+7
    const int aRow = tid >> 1;
    const int aC   = (tid & 1) * 8;
    // B loader: row = tid>>4 (0..15), cols bC..bC+7
    const int bRow = tid >> 4;
    const int bC   = (tid & 15) * 8;

    const float* Aptr = A + (m0 + aRow) * DM + aC;
    const float* Wptr = W + bRow * DM + n0 + bC;

    float acc[8][8];
    #pragma unroll
    for (int i = 0; i < 8; i++)
        #pragma unroll
        for (int j = 0; j < 8; j++) acc[i][j] = 0.0f;

    // Prefetch first tile into registers
    float4 aP0 = *(const float4*)(Aptr + 0);
    float4 aP1 = *(const float4*)(Aptr + 4);
    float4 bP0 = *(const float4*)(Wptr + 0);
    float4 bP1 = *(const float4*)(Wptr + 4);

    for (int k0 = 0; k0 < DM; k0 += 16) {
        __syncthreads();   // previous tile's compute finished
        // Store prefetched tile to smem (A transposed to [k][m])
        As[(aC + 0) * 132 + aRow] = aP0.x;
        As[(aC + 1) * 132 + aRow] = aP0.y;
        As[(aC + 2) * 132 + aRow] = aP0.z;
        As[(aC + 3) * 132 + aRow] = aP0.w;
        As[(aC + 4) * 132 + aRow] = aP1.x;
        As[(aC + 5) * 132 + aRow] = aP1.y;
        As[(aC + 6) * 132 + aRow] = aP1.z;
        As[(aC + 7) * 132 + aRow] = aP1.w;
        *(float4*)&Bs[bRow * 128 + bC + 0] = bP0;
        *(float4*)&Bs[bRow * 128 + bC + 4] = bP1;
        __syncthreads();

        // Prefetch next tile (overlaps with compute below)
        if (k0 + 16 < DM) {
            Aptr += 16;
            Wptr += 16 * DM;
            aP0 = *(const float4*)(Aptr + 0);
            aP1 = *(const float4*)(Aptr + 4);
            bP0 = *(const float4*)(Wptr + 0);
            bP1 = *(const float4*)(Wptr + 4);
        }

        #pragma unroll
        for (int kk = 0; kk < 16; kk++) {
            float4 a0 = *(const float4*)&As[kk * 132 + ty * 8 + 0];
            float4 a1 = *(const float4*)&As[kk * 132 + ty * 8 + 4];
            float4 b0 = *(const float4*)&Bs[kk * 128 + tx * 8 + 0];
            float4 b1 = *(const float4*)&Bs[kk * 128 + tx * 8 + 4];
            float ar[8] = {a0.x, a0.y, a0.z, a0.w, a1.x, a1.y, a1.z, a1.w};
            float br[8] = {b0.x, b0.y, b0.z, b0.w, b1.x, b1.y, b1.z, b1.w};
            #pragma unroll
            for (int i = 0; i < 8; i++)
                #pragma unroll
                for (int j = 0; j < 8; j++)
                    acc[i][j] = fmaf(ar[i], br[j], acc[i][j]);
        }
    }

    float4 bias0 = *(const float4*)&bias[n0 + tx * 8 + 0];
    float4 bias1 = *(const float4*)&bias[n0 + tx * 8 + 4];
    #pragma unroll
    for (int i = 0; i < 8; i++) {
        int m = m0 + ty * 8 + i;
        float4 r0, r1;
        r0.x = acc[i][0] + bias0.x;
        r0.y = acc[i][1] + bias0.y;
        r0.z = acc[i][2] + bias0.z;
        r0.w = acc[i][3] + bias0.w;
        r1.x = acc[i][4] + bias1.x;
        r1.y = acc[i][5] + bias1.y;
        r1.z = acc[i][6] + bias1.z;
        r1.w = acc[i][7] + bias1.w;
        *(float4*)&C[m * DM + n0 + tx * 8 + 0] = r0;
        *(float4*)&C[m * DM + n0 + tx * 8 + 4] = r1;
    }
}

// ---------------------------------------------------------------------------
// Windowed attention per (tile of 64 queries, head, batch) + per-tile pooling.
// smem: q(64x68) | k(128x68) | v(128x68) | attn(64x68)  = 104448 B dynamic
// ---------------------------------------------------------------------------
__global__ __launch_bounds__(256) void attn_kernel()
{
    const int tile = blockIdx.x;   // 0..15
    const int h    = blockIdx.y;   // 0..11
    const int b    = blockIdx.z;   // 0..1
    const int s0   = tile * 64;
    const int colbase = h * HD;

    extern __shared__ float sm[];
    float* q_sm = sm;                    // 64*68
    float* k_sm = q_sm + 64 * 68;        // 128*68
    float* v_sm = k_sm + 128 * 68;       // 128*68
    float* a_sm = v_sm + 128 * 68;       // 64*68 (scores/attn, then reduce buf)

    const int tid = threadIdx.x;

    // Load Q tile (64 rows x 64 dims)
    for (int i = tid; i < 64 * 16; i += 256) {
        int row = i >> 4;
        int c4  = (i & 15) << 2;
        float4 v = *(const float4*)&g_q[((b * S_LEN) + s0 + row) * DM + colbase + c4];
        *(float4*)&q_sm[row * 68 + c4] = v;
    }
    // Load K/V window (rows s0-32 .. s0+95), zero-fill out of range
    for (int i = tid; i < 128 * 16; i += 256) {
        int row  = i >> 4;
        int c4   = (i & 15) << 2;
        int srow = s0 - 32 + row;
        float4 kv = make_float4(0.f, 0.f, 0.f, 0.f);
        float4 vv = make_float4(0.f, 0.f, 0.f, 0.f);
        if (srow >= 0 && srow < S_LEN) {
            kv = *(const float4*)&g_k[((b * S_LEN) + srow) * DM + colbase + c4];
            vv = *(const float4*)&g_v[((b * S_LEN) + srow) * DM + colbase + c4];
        }
        *(float4*)&k_sm[row * 68 + c4] = kv;
        *(float4*)&v_sm[row * 68 + c4] = vv;
    }
    __syncthreads();

    const int qi  = tid >> 2;       // query within tile
    const int sub = tid & 3;        // sub-lane within query group
    const int sglob = s0 + qi;

    // ---- scores for window positions w = sub, sub+4, ... (<=64) ----
    float sc[17];
    const int nw = (sub == 0) ? 17 : 16;
    const float* qr = &q_sm[qi * 68];
    for (int j = 0; j < nw; j++) {
        int w = sub + 4 * j;
        const float* kr = &k_sm[(qi + w) * 68];
        float s = 0.f;
        #pragma unroll
        for (int dc = 0; dc < 16; dc++) {
            float4 qv = *(const float4*)&qr[dc * 4];
            float4 kv = *(const float4*)&kr[dc * 4];
            s = fmaf(qv.x, kv.x, s);
            s = fmaf(qv.y, kv.y, s);
            s = fmaf(qv.z, kv.z, s);
            s = fmaf(qv.w, kv.w, s);
        }
        int ks = sglob - 32 + w;
        sc[j] = (ks >= 0 && ks < S_LEN) ? s * 0.125f : -1e9f;
    }

    // ---- softmax across the 4-lane group ----
    float m = -1e30f;
    for (int j = 0; j < nw; j++) m = fmaxf(m, sc[j]);
    m = fmaxf(m, __shfl_xor_sync(0xffffffffu, m, 1));
    m = fmaxf(m, __shfl_xor_sync(0xffffffffu, m, 2));
    float lsum = 0.f;
    for (int j = 0; j < nw; j++) { sc[j] = __expf(sc[j] - m); lsum += sc[j]; }
    lsum += __shfl_xor_sync(0xffffffffu, lsum, 1);
    lsum += __shfl_xor_sync(0xffffffffu, lsum, 2);
    float rinv = 1.0f / lsum;
    for (int j = 0; j < nw; j++)
        a_sm[qi * 68 + sub + 4 * j] = sc[j] * rinv;
    __syncthreads();

    // ---- out[qi][d0..d0+15] = sum_w attn * v ----
    const int d0 = sub * 16;
    float4 acc0 = make_float4(0.f, 0.f, 0.f, 0.f);
    float4 acc1 = acc0, acc2 = acc0, acc3 = acc0;
    const float* ar = &a_sm[qi * 68];
    for (int w = 0; w < 65; w++) {
        float p = ar[w];
        const float* vr = &v_sm[(qi + w) * 68 + d0];
        float4 v0 = *(const float4*)&vr[0];
        float4 v1 = *(const float4*)&vr[4];
        float4 v2 = *(const float4*)&vr[8];
        float4 v3 = *(const float4*)&vr[12];
        acc0.x = fmaf(p, v0.x, acc0.x); acc0.y = fmaf(p, v0.y, acc0.y);
        acc0.z = fmaf(p, v0.z, acc0.z); acc0.w = fmaf(p, v0.w, acc0.w);
        acc1.x = fmaf(p, v1.x, acc1.x); acc1.y = fmaf(p, v1.y, acc1.y);
        acc1.z = fmaf(p, v1.z, acc1.z); acc1.w = fmaf(p, v1.w, acc1.w);
        acc2.x = fmaf(p, v2.x, acc2.x); acc2.y = fmaf(p, v2.y, acc2.y);
        acc2.z = fmaf(p, v2.z, acc2.z); acc2.w = fmaf(p, v2.w, acc2.w);
        acc3.x = fmaf(p, v3.x, acc3.x); acc3.y = fmaf(p, v3.y, acc3.y);
        acc3.z = fmaf(p, v3.z, acc3.z); acc3.w = fmaf(p, v3.w, acc3.w);
    }

    // Store per-query outputs into q_sm (safe: q_sm reads ended before prior barrier)
    *(float4*)&q_sm[qi * 68 + d0 + 0]  = acc0;
    *(float4*)&q_sm[qi * 68 + d0 + 4]  = acc1;
    *(float4*)&q_sm[qi * 68 + d0 + 8]  = acc2;
    *(float4*)&q_sm[qi * 68 + d0 + 12] = acc3;
    __syncthreads();

    // ---- pooled partial: sum over the 64 queries in this tile ----
    const int d    = tid & 63;
    const int part = tid >> 6;
    float s = 0.f;
    #pragma unroll
    for (int r = part * 16; r < part * 16 + 16; r++)
        s += q_sm[r * 68 + d];
    a_sm[part * 64 + d] = s;
    __syncthreads();
    if (tid < 64) {
        float tot = a_sm[tid] + a_sm[64 + tid] + a_sm[128 + tid] + a_sm[192 + tid];
        g_part[((b * NTILE) + tile) * DM + h * HD + tid] = tot;
    }
}

// ---------------------------------------------------------------------------
// Final FC: out[b][o] = relu( (mean_s out_attn)[b] @ Wfc + bfc )
// ---------------------------------------------------------------------------
__global__ __launch_bounds__(256) void fc_kernel(
    const float* __restrict__ Wfc, const float* __restrict__ bfc,
    float* __restrict__ out)
{
    __shared__ float pooled[DM];
    const int b   = blockIdx.y;
    const int tid = threadIdx.x;

    for (int i = tid; i < DM; i += 256) {
        float s = 0.f;
        #pragma unroll
        for (int t = 0; t < NTILE; t++)
            s += g_part[(b * NTILE + t) * DM + i];
        pooled[i] = s * (1.0f / (float)S_LEN);
    }
    __syncthreads();

    const int o = blockIdx.x * 256 + tid;
    float acc = bfc[o];
    for (int i = 0; i < DM; i++)
        acc = fmaf(pooled[i], Wfc[i * DM + o], acc);
    out[b * DM + o] = fmaxf(acc, 0.f);
}

// ---------------------------------------------------------------------------
extern "C" void kernel_launch(void* const* d_in, const int* in_sizes, int n_in,
                              void* d_out, int out_size)
{
    const float* x   = (const float*)d_in[0];
    const float* Wq  = (const float*)d_in[1];
    const float* bq  = (const float*)d_in[2];
    const float* Wk  = (const float*)d_in[3];
    const float* bk  = (const float*)d_in[4];
    const float* Wv  = (const float*)d_in[5];
    const float* bv  = (const float*)d_in[6];
    const float* Wfc = (const float*)d_in[7];
    const float* bfc = (const float*)d_in[8];
    float* out = (float*)d_out;

    // QKV projections: 128x128 tiles
    dim3 gg(DM / 128, (BATCH * S_LEN) / 128, 3);
    qkv_gemm<<<gg, 256>>>(x, Wq, bq, Wk, bk, Wv, bv);

    // Windowed attention + per-tile pooling (104448 B dynamic smem)
    const int attn_smem = (64 + 128 + 128 + 64) * 68 * (int)sizeof(float);
    cudaFuncSetAttribute(attn_kernel,
                         cudaFuncAttributeMaxDynamicSharedMemorySize, attn_smem);
    attn_kernel<<<dim3(NTILE, NH, BATCH), 256, attn_smem>>>();

    // Pool + FC + relu
    fc_kernel<<<dim3(3, BATCH), 256>>>(Wfc, bfc, out);
}